// round 13
// baseline (speedup 1.0000x reference)
#include <cuda_runtime.h>
#include <math.h>
#include <stdint.h>

#define N_NODES 100000
#define N_EDGES 3200000
#define K_IN    1433
#define C1      16

// ---------------- scratch (static device globals; no allocation) ------------
__device__ __align__(16) int   g_cnt[N_NODES];
__device__ __align__(16) int   g_off[N_NODES + 4];
__device__ __align__(16) int   g_pos[N_NODES];
__device__ __align__(16) float g_dinv[N_NODES];
__device__ __align__(16) int   g_ecol[N_EDGES];
__device__ __align__(16) float g_h1[N_NODES * 16];
__device__ __align__(16) float g_h1b[N_NODES * 16];
__device__ __align__(16) float g_h2[N_NODES * 8];

// ---------------- degree / CSR build ---------------------------------------
__global__ void k_zero_cnt() {
    int i = blockIdx.x * blockDim.x + threadIdx.x;
    if (i * 4 < N_NODES) ((int4*)g_cnt)[i] = make_int4(0, 0, 0, 0);
}

__global__ void k_count(const int* __restrict__ row) {
    int i = blockIdx.x * blockDim.x + threadIdx.x;
    if (i * 8 >= N_EDGES) return;
    int4 r0 = ((const int4*)row)[2 * i];
    int4 r1 = ((const int4*)row)[2 * i + 1];
    atomicAdd(&g_cnt[r0.x], 1);
    atomicAdd(&g_cnt[r0.y], 1);
    atomicAdd(&g_cnt[r0.z], 1);
    atomicAdd(&g_cnt[r0.w], 1);
    atomicAdd(&g_cnt[r1.x], 1);
    atomicAdd(&g_cnt[r1.y], 1);
    atomicAdd(&g_cnt[r1.z], 1);
    atomicAdd(&g_cnt[r1.w], 1);
}

__global__ void k_scan() {
    const int T = 1024, ACT = 1000, CH4 = 25;
    int t = threadIdx.x;
    __shared__ int ps[T];
    int sum = 0;
    if (t < ACT) {
        const int4* c4 = (const int4*)g_cnt + t * CH4;
#pragma unroll
        for (int i = 0; i < CH4; i++) { int4 v = c4[i]; sum += v.x + v.y + v.z + v.w; }
    }
    ps[t] = sum;
    __syncthreads();
    for (int off = 1; off < T; off <<= 1) {
        int v = (t >= off) ? ps[t - off] : 0;
        __syncthreads();
        ps[t] += v;
        __syncthreads();
    }
    if (t < ACT) {
        int run = (t > 0) ? ps[t - 1] : 0;
        const int4* c4 = (const int4*)g_cnt + t * CH4;
        int4*   o4 = (int4*)g_off + t * CH4;
        int4*   p4 = (int4*)g_pos + t * CH4;
        float4* d4 = (float4*)g_dinv + t * CH4;
#pragma unroll 5
        for (int i = 0; i < CH4; i++) {
            int4 v = c4[i];
            int4 o;
            o.x = run; o.y = o.x + v.x; o.z = o.y + v.y; o.w = o.z + v.z;
            run = o.w + v.w;
            o4[i] = o; p4[i] = o;
            float4 dv;
            dv.x = rsqrtf((float)(v.x + 1)); dv.y = rsqrtf((float)(v.y + 1));
            dv.z = rsqrtf((float)(v.z + 1)); dv.w = rsqrtf((float)(v.w + 1));
            d4[i] = dv;
        }
        if (t == ACT - 1) g_off[N_NODES] = run;
    }
}

__global__ void k_place(const int* __restrict__ row, const int* __restrict__ col) {
    int i = blockIdx.x * blockDim.x + threadIdx.x;
    if (i * 8 >= N_EDGES) return;
    int4 r0 = ((const int4*)row)[2 * i];
    int4 r1 = ((const int4*)row)[2 * i + 1];
    int4 c0 = ((const int4*)col)[2 * i];
    int4 c1 = ((const int4*)col)[2 * i + 1];
    int p0 = atomicAdd(&g_pos[r0.x], 1);
    int p1 = atomicAdd(&g_pos[r0.y], 1);
    int p2 = atomicAdd(&g_pos[r0.z], 1);
    int p3 = atomicAdd(&g_pos[r0.w], 1);
    int p4 = atomicAdd(&g_pos[r1.x], 1);
    int p5 = atomicAdd(&g_pos[r1.y], 1);
    int p6 = atomicAdd(&g_pos[r1.z], 1);
    int p7 = atomicAdd(&g_pos[r1.w], 1);
    g_ecol[p0] = c0.x;
    g_ecol[p1] = c0.y;
    g_ecol[p2] = c0.z;
    g_ecol[p3] = c0.w;
    g_ecol[p4] = c1.x;
    g_ecol[p5] = c1.y;
    g_ecol[p6] = c1.z;
    g_ecol[p7] = c1.w;
}

// ------------- GEMM1, k-SPLIT x2 CTAs/SM: h1 = x@W1[0:720], h1b = rest -------
// R8's proven cp.async kernel, parameterized by k0. Each CTA holds only its
// 720-row W slice (45KB) + 3 staging stages -> 112KB smem -> 2 CTAs/SM.
// Two independent barrier domains per SM cover each other's stalls.
#define G1_BLOCK 256
#define G1_KT    8
#define G1_MT    680
#define G1_MTP   681
#define G1_NT    90             // 90 8-wide local tiles (720 k rows, padded)
#define G1_NU    22
#define G1_HALF  148            // blocks per half; grid = 296
#define K0_B     720            // half B start; A: k 0..719 (full), B: 720..1432
#define STAGES   3
#define STAGE_FLOATS (G1_KT * G1_MTP)       // 5448
#define WS_ROWS  720
#define WS_FLOATS (WS_ROWS * C1)            // 11520
// +128 pad: masked compute rows read up to 86 floats past the last stage.
#define G1_SMEM_FLOATS (WS_FLOATS + STAGES * STAGE_FLOATS + 128)
#define G1_SMEM_BYTES  (G1_SMEM_FLOATS * 4)   // 111,968 B -> 2 CTAs = 223,936

__device__ __forceinline__ void ffma2(unsigned long long& d,
                                      unsigned long long a,
                                      unsigned long long b) {
    asm("fma.rn.f32x2 %0, %1, %2, %0;" : "+l"(d) : "l"(a), "l"(b));
}
__device__ __forceinline__ void cp_async4(unsigned dst, const float* src) {
    asm volatile("cp.async.ca.shared.global [%0], [%1], 4;" :: "r"(dst), "l"(src));
}
__device__ __forceinline__ void cp_commit() {
    asm volatile("cp.async.commit_group;");
}
__device__ __forceinline__ void cp_wait1() {
    asm volatile("cp.async.wait_group 1;");
}

__global__ void __launch_bounds__(G1_BLOCK, 2)
k_gemm1(const float* __restrict__ x, const float* __restrict__ W1) {
    extern __shared__ float sm[];
    float* ws = sm;                       // [720 * 16]; tail rows zeroed
    float* xs = sm + WS_FLOATS;           // [STAGES][8 * 681] (+128 pad)

    const int half = (blockIdx.x >= G1_HALF) ? 1 : 0;
    const int bid  = blockIdx.x - half * G1_HALF;
    const int k0   = half * K0_B;
    float* __restrict__ hout = half ? g_h1b : g_h1;

    const int tid = threadIdx.x;
    const int m0  = bid * G1_MT;
    const int kk  = tid & 7;
    const int mb  = tid >> 3;

    // load this half's W slice (zero-pad local rows past K_IN)
    {
        const float4* W4  = (const float4*)W1;
        float4*       ws4 = (float4*)ws;
        for (int i = tid; i < WS_FLOATS / 4; i += G1_BLOCK) {
            int gk = k0 + (i >> 2);            // 4 float4 per 16-col row
            float4 v = make_float4(0.f, 0.f, 0.f, 0.f);
            if (gk < K_IN) v = W4[gk * 4 + (i & 3)];
            ws4[i] = v;
        }
    }

    bool mval[G1_NU];
#pragma unroll
    for (int u = 0; u < G1_NU; u++) {
        int m = mb + 32 * u;
        mval[u] = (m < G1_MT) && (m0 + m < N_NODES);
    }
    const float* xsrc0 = x + (size_t)(m0 + mb) * K_IN + k0 + kk;
    const unsigned xs_u32 = (unsigned)__cvta_generic_to_shared(xs);
    const unsigned dst0 = xs_u32 + (unsigned)(kk * G1_MTP + mb) * 4u;

    unsigned long long acc2[3][8];
#pragma unroll
    for (int r = 0; r < 3; r++)
#pragma unroll
        for (int c = 0; c < 8; c++) acc2[r][c] = 0ull;

    // prologue: issue tiles 0, 1 into stages 0, 1
#pragma unroll
    for (int t = 0; t < 2; t++) {
        bool kv = (k0 + 8 * t + kk) < K_IN;
        unsigned dst = dst0 + (unsigned)((t % STAGES) * STAGE_FLOATS) * 4u;
        const float* src = xsrc0 + 8 * t;
#pragma unroll
        for (int u = 0; u < G1_NU; u++)
            if (mval[u] && kv) cp_async4(dst + u * 128u, src + (size_t)u * 32 * K_IN);
        cp_commit();
    }

    for (int t = 0; t < G1_NT; t++) {
        cp_wait1();          // tile t landed (t+1 may be in flight)
        __syncthreads();     // all threads' waits done; stage (t+2)%3 free

        if (t + 2 < G1_NT) {
            int tn = t + 2;
            bool kv = (k0 + 8 * tn + kk) < K_IN;
            unsigned dst = dst0 + (unsigned)((tn % STAGES) * STAGE_FLOATS) * 4u;
            const float* src = xsrc0 + 8 * tn;
#pragma unroll
            for (int u = 0; u < G1_NU; u++)
                if (mval[u] && kv) cp_async4(dst + u * 128u, src + (size_t)u * 32 * K_IN);
        }
        cp_commit();

        const float* xb = xs + (t % STAGES) * STAGE_FLOATS;
#pragma unroll
        for (int k = 0; k < G1_KT; k++) {
            const ulonglong2* wrow = (const ulonglong2*)(ws + (t * G1_KT + k) * C1);
            ulonglong2 wa = wrow[0], wb = wrow[1], wc = wrow[2], wd = wrow[3];
#pragma unroll
            for (int r = 0; r < 3; r++) {
                float xv = xb[k * G1_MTP + (r * G1_BLOCK + tid)];
                unsigned long long xv2;
                asm("mov.b64 %0, {%1, %1};" : "=l"(xv2) : "f"(xv));
                ffma2(acc2[r][0], xv2, wa.x);
                ffma2(acc2[r][1], xv2, wa.y);
                ffma2(acc2[r][2], xv2, wb.x);
                ffma2(acc2[r][3], xv2, wb.y);
                ffma2(acc2[r][4], xv2, wc.x);
                ffma2(acc2[r][5], xv2, wc.y);
                ffma2(acc2[r][6], xv2, wd.x);
                ffma2(acc2[r][7], xv2, wd.y);
            }
        }
    }

#pragma unroll
    for (int r = 0; r < 3; r++) {
        int lm = r * G1_BLOCK + tid;
        int m  = m0 + lm;
        if (lm < G1_MT && m < N_NODES) {
            float4* o = (float4*)(hout + (size_t)m * 16);
#pragma unroll
            for (int p = 0; p < 4; p++) {
                float2 f0, f1;
                asm("mov.b64 {%0, %1}, %2;" : "=f"(f0.x), "=f"(f0.y) : "l"(acc2[r][2 * p]));
                asm("mov.b64 {%0, %1}, %2;" : "=f"(f1.x), "=f"(f1.y) : "l"(acc2[r][2 * p + 1]));
                o[p] = make_float4(f0.x, f0.y, f1.x, f1.y);
            }
        }
    }
}

// ---------------- h1 = h1 + h1b (merge the two k-halves) ---------------------
__global__ void k_h1sum() {
    int i = blockIdx.x * blockDim.x + threadIdx.x;
    if (i >= N_NODES * 4) return;        // float4 count
    float4 a = ((const float4*)g_h1)[i];
    float4 b = ((const float4*)g_h1b)[i];
    ((float4*)g_h1)[i] = make_float4(a.x + b.x, a.y + b.y, a.z + b.z, a.w + b.w);
}

// -------- aggregation 1 + bias + relu + GEMM2 fused: ONE WARP PER NODE -------
__global__ void __launch_bounds__(256)
k_agg1(const float* __restrict__ b1, const float* __restrict__ W2) {
    __shared__ float w2s[16 * 7];
    if (threadIdx.x < 16 * 7) w2s[threadIdx.x] = W2[threadIdx.x];
    __syncthreads();

    int g = (blockIdx.x * blockDim.x + threadIdx.x) >> 5;
    if (g >= N_NODES) return;
    int lane = threadIdx.x & 31;
    int e = lane >> 2, q = lane & 3;

    int s = g_off[g];
    int deg = g_off[g + 1] - s;
    const int* cols = g_ecol + s;

    float4 acc = make_float4(0.f, 0.f, 0.f, 0.f);
    for (int i = e; i < deg; i += 8) {
        int c = __ldg(cols + i);
        float dw = g_dinv[c];
        float4 hv = *(const float4*)(g_h1 + (size_t)c * 16 + q * 4);
        acc.x += hv.x * dw; acc.y += hv.y * dw;
        acc.z += hv.z * dw; acc.w += hv.w * dw;
    }

#pragma unroll
    for (int o = 16; o >= 4; o >>= 1) {
        acc.x += __shfl_xor_sync(0xffffffffu, acc.x, o);
        acc.y += __shfl_xor_sync(0xffffffffu, acc.y, o);
        acc.z += __shfl_xor_sync(0xffffffffu, acc.z, o);
        acc.w += __shfl_xor_sync(0xffffffffu, acc.w, o);
    }

    float di = g_dinv[g];
    float4 self = *(const float4*)(g_h1 + (size_t)g * 16 + q * 4);
    float4 bb   = ((const float4*)b1)[q];
    float v0 = fmaxf(bb.x + di * (acc.x + di * self.x), 0.f);
    float v1 = fmaxf(bb.y + di * (acc.y + di * self.y), 0.f);
    float v2 = fmaxf(bb.z + di * (acc.z + di * self.z), 0.f);
    float v3 = fmaxf(bb.w + di * (acc.w + di * self.w), 0.f);

    float h2a[7];
    const float* w2r = w2s + (4 * q) * 7;
#pragma unroll
    for (int c2 = 0; c2 < 7; c2++)
        h2a[c2] = v0 * w2r[c2] + v1 * w2r[7 + c2] + v2 * w2r[14 + c2] + v3 * w2r[21 + c2];
#pragma unroll
    for (int o = 1; o <= 2; o <<= 1)
#pragma unroll
        for (int c2 = 0; c2 < 7; c2++)
            h2a[c2] += __shfl_xor_sync(0xffffffffu, h2a[c2], o);

    if (lane == 0) {
        float4* o4 = (float4*)(g_h2 + (size_t)g * 8);
        o4[0] = make_float4(h2a[0], h2a[1], h2a[2], h2a[3]);
        o4[1] = make_float4(h2a[4], h2a[5], h2a[6], 0.f);
    }
}

// -------- aggregation 2 + bias + log_softmax: ONE WARP PER NODE --------------
__global__ void __launch_bounds__(256)
k_agg2(const float* __restrict__ b2, float* __restrict__ out) {
    int g = (blockIdx.x * blockDim.x + threadIdx.x) >> 5;
    if (g >= N_NODES) return;
    int lane = threadIdx.x & 31;
    int e = lane >> 2, q = lane & 3;

    int s = g_off[g];
    int deg = g_off[g + 1] - s;
    const int* cols = g_ecol + s;

    float a0 = 0.f, a1 = 0.f;
    for (int i = e; i < deg; i += 8) {
        int c = __ldg(cols + i);
        float dw = g_dinv[c];
        float2 hv = *(const float2*)(g_h2 + (size_t)c * 8 + q * 2);
        a0 += hv.x * dw;
        a1 += hv.y * dw;
    }
#pragma unroll
    for (int o = 16; o >= 4; o >>= 1) {
        a0 += __shfl_xor_sync(0xffffffffu, a0, o);
        a1 += __shfl_xor_sync(0xffffffffu, a1, o);
    }

    float di = g_dinv[g];
    float dd = di * di;
    float2 self = *(const float2*)(g_h2 + (size_t)g * 8 + q * 2);
    float bb0 = b2[2 * q];
    float bb1 = (q < 3) ? b2[2 * q + 1] : 0.f;
    a0 = bb0 + di * a0 + dd * self.x;
    a1 = bb1 + di * a1 + dd * self.y;

    float m = (q == 3) ? a0 : fmaxf(a0, a1);
    m = fmaxf(m, __shfl_xor_sync(0xffffffffu, m, 1, 4));
    m = fmaxf(m, __shfl_xor_sync(0xffffffffu, m, 2, 4));
    float e0 = expf(a0 - m);
    float e1 = (q == 3) ? 0.f : expf(a1 - m);
    float ss = e0 + e1;
    ss += __shfl_xor_sync(0xffffffffu, ss, 1, 4);
    ss += __shfl_xor_sync(0xffffffffu, ss, 2, 4);
    float ls = m + logf(ss);

    if (e == 0) {
        out[(size_t)g * 7 + 2 * q] = a0 - ls;
        if (q < 3) out[(size_t)g * 7 + 2 * q + 1] = a1 - ls;
    }
}

// ---------------- launch ------------------------------------------------------
static cudaStream_t s_csr = 0;
static cudaEvent_t  ev_fork = 0, ev_join = 0;

extern "C" void kernel_launch(void* const* d_in, const int* in_sizes, int n_in,
                              void* d_out, int out_size) {
    const float* x   = (const float*)d_in[0];
    const int*   row = (const int*)  d_in[1];
    const int*   col = (const int*)  d_in[2];
    const float* W1  = (const float*)d_in[3];
    const float* b1  = (const float*)d_in[4];
    const float* W2  = (const float*)d_in[5];
    const float* b2  = (const float*)d_in[6];
    float* out = (float*)d_out;

    if (!s_csr) {
        cudaStreamCreateWithFlags(&s_csr, cudaStreamNonBlocking);
        cudaEventCreateWithFlags(&ev_fork, cudaEventDisableTiming);
        cudaEventCreateWithFlags(&ev_join, cudaEventDisableTiming);
        cudaFuncSetAttribute(k_gemm1, cudaFuncAttributeMaxDynamicSharedMemorySize,
                             G1_SMEM_BYTES);
    }

    // fork: CSR chain onto side stream (overlaps with GEMM1)
    cudaEventRecord(ev_fork, 0);
    cudaStreamWaitEvent(s_csr, ev_fork, 0);

    k_zero_cnt<<<(N_NODES / 4 + 255) / 256, 256, 0, s_csr>>>();
    k_count   <<<(N_EDGES / 8 + 255) / 256, 256, 0, s_csr>>>(row);
    k_scan    <<<1, 1024, 0, s_csr>>>();

    // main stream: GEMM1, both k-halves in one grid (2 CTAs co-resident/SM)
    k_gemm1<<<2 * G1_HALF, G1_BLOCK, G1_SMEM_BYTES>>>(x, W1);
    k_h1sum<<<(N_NODES * 4 + 255) / 256, 256>>>();

    k_place<<<(N_EDGES / 8 + 255) / 256, 256, 0, s_csr>>>(row, col);

    // join: aggregation needs both CSR and h1
    cudaEventRecord(ev_join, s_csr);
    cudaStreamWaitEvent(0, ev_join, 0);

    k_agg1<<<(N_NODES * 32 + 255) / 256, 256>>>(b1, W2);
    k_agg2<<<(N_NODES * 32 + 255) / 256, 256>>>(b2, out);
}

// round 14
// speedup vs baseline: 1.5623x; 1.5623x over previous
#include <cuda_runtime.h>
#include <math.h>
#include <stdint.h>

#define N_NODES 100000
#define N_EDGES 3200000
#define K_IN    1433
#define C1      16

// ---------------- scratch (static device globals; no allocation) ------------
__device__ __align__(16) int   g_cnt[N_NODES];
__device__ __align__(16) int   g_off[N_NODES + 4];
__device__ __align__(16) int   g_pos[N_NODES];
__device__ __align__(16) float g_dinv[N_NODES];
__device__ __align__(16) int   g_ecol[N_EDGES];
__device__ __align__(16) float g_h1[N_NODES * 16];
__device__ __align__(16) float g_h2[N_NODES * 8];

// ---------------- degree / CSR build ---------------------------------------
__global__ void k_zero_cnt() {
    int i = blockIdx.x * blockDim.x + threadIdx.x;
    if (i * 4 < N_NODES) ((int4*)g_cnt)[i] = make_int4(0, 0, 0, 0);
}

__global__ void k_count(const int* __restrict__ row) {
    int i = blockIdx.x * blockDim.x + threadIdx.x;
    if (i * 8 >= N_EDGES) return;
    int4 r0 = ((const int4*)row)[2 * i];
    int4 r1 = ((const int4*)row)[2 * i + 1];
    atomicAdd(&g_cnt[r0.x], 1);
    atomicAdd(&g_cnt[r0.y], 1);
    atomicAdd(&g_cnt[r0.z], 1);
    atomicAdd(&g_cnt[r0.w], 1);
    atomicAdd(&g_cnt[r1.x], 1);
    atomicAdd(&g_cnt[r1.y], 1);
    atomicAdd(&g_cnt[r1.z], 1);
    atomicAdd(&g_cnt[r1.w], 1);
}

__global__ void k_scan() {
    const int T = 1024, ACT = 1000, CH4 = 25;
    int t = threadIdx.x;
    __shared__ int ps[T];
    int sum = 0;
    if (t < ACT) {
        const int4* c4 = (const int4*)g_cnt + t * CH4;
#pragma unroll
        for (int i = 0; i < CH4; i++) { int4 v = c4[i]; sum += v.x + v.y + v.z + v.w; }
    }
    ps[t] = sum;
    __syncthreads();
    for (int off = 1; off < T; off <<= 1) {
        int v = (t >= off) ? ps[t - off] : 0;
        __syncthreads();
        ps[t] += v;
        __syncthreads();
    }
    if (t < ACT) {
        int run = (t > 0) ? ps[t - 1] : 0;
        const int4* c4 = (const int4*)g_cnt + t * CH4;
        int4*   o4 = (int4*)g_off + t * CH4;
        int4*   p4 = (int4*)g_pos + t * CH4;
        float4* d4 = (float4*)g_dinv + t * CH4;
#pragma unroll 5
        for (int i = 0; i < CH4; i++) {
            int4 v = c4[i];
            int4 o;
            o.x = run; o.y = o.x + v.x; o.z = o.y + v.y; o.w = o.z + v.z;
            run = o.w + v.w;
            o4[i] = o; p4[i] = o;
            float4 dv;
            dv.x = rsqrtf((float)(v.x + 1)); dv.y = rsqrtf((float)(v.y + 1));
            dv.z = rsqrtf((float)(v.z + 1)); dv.w = rsqrtf((float)(v.w + 1));
            d4[i] = dv;
        }
        if (t == ACT - 1) g_off[N_NODES] = run;
    }
}

__global__ void k_place(const int* __restrict__ row, const int* __restrict__ col) {
    int i = blockIdx.x * blockDim.x + threadIdx.x;
    if (i * 8 >= N_EDGES) return;
    int4 r0 = ((const int4*)row)[2 * i];
    int4 r1 = ((const int4*)row)[2 * i + 1];
    int4 c0 = ((const int4*)col)[2 * i];
    int4 c1 = ((const int4*)col)[2 * i + 1];
    int p0 = atomicAdd(&g_pos[r0.x], 1);
    int p1 = atomicAdd(&g_pos[r0.y], 1);
    int p2 = atomicAdd(&g_pos[r0.z], 1);
    int p3 = atomicAdd(&g_pos[r0.w], 1);
    int p4 = atomicAdd(&g_pos[r1.x], 1);
    int p5 = atomicAdd(&g_pos[r1.y], 1);
    int p6 = atomicAdd(&g_pos[r1.z], 1);
    int p7 = atomicAdd(&g_pos[r1.w], 1);
    g_ecol[p0] = c0.x;
    g_ecol[p1] = c0.y;
    g_ecol[p2] = c0.z;
    g_ecol[p3] = c0.w;
    g_ecol[p4] = c1.x;
    g_ecol[p5] = c1.y;
    g_ecol[p6] = c1.z;
    g_ecol[p7] = c1.w;
}

// -------- GEMM1: warp-private cp.async pipelines (NO block barriers) ---------
// Each warp owns 96 rows + a private 4-stage staging ring. Lane issues k=lane&7
// for rows (lane>>3)+4j (j=0..23). Staging slot = k*96 + (rowl ^ 4k): XOR keeps
// slots inside the same 32-row block (stage exactly 768 floats) and makes both
// the LDGSTS smem-write side and the compute LDS side bank-conflict-free.
#define G1_BLOCK 256
#define G1_MT    768                // 8 warps * 96 rows
#define G1_GRID  131                // ceil(100000/768)
#define G1_NT    180                // tile 179: only k=1432 valid (kv guard)
#define RPW      96
#define STAGES   4
#define STG_F    768                // floats per warp-stage (8k * 96 rows)
#define WS_PAD_K 1440
#define WS_FLOATS (WS_PAD_K * C1)   // 23040, rows 1433.. zeroed
#define G1_SMEM_FLOATS (WS_FLOATS + 8 * STAGES * STG_F + 16)
#define G1_SMEM_BYTES  (G1_SMEM_FLOATS * 4)   // 190,528 B

__device__ __forceinline__ void ffma2(unsigned long long& d,
                                      unsigned long long a,
                                      unsigned long long b) {
    asm("fma.rn.f32x2 %0, %1, %2, %0;" : "+l"(d) : "l"(a), "l"(b));
}
__device__ __forceinline__ void cp_async4(unsigned dst, const float* src) {
    asm volatile("cp.async.ca.shared.global [%0], [%1], 4;" :: "r"(dst), "l"(src));
}
__device__ __forceinline__ void cp_commit() {
    asm volatile("cp.async.commit_group;");
}
__device__ __forceinline__ void cp_wait2() {
    asm volatile("cp.async.wait_group 2;");
}

__global__ void __launch_bounds__(G1_BLOCK, 1)
k_gemm1(const float* __restrict__ x, const float* __restrict__ W1) {
    extern __shared__ float sm[];
    float* ws = sm;                          // [1440 * 16]
    float* xs = sm + WS_FLOATS;              // [8 warps][4 stages][768]

    const int tid  = threadIdx.x;
    const int w    = tid >> 5;
    const int lane = tid & 31;
    const int kk   = lane & 7;               // this lane's copy-k
    const int rowb = lane >> 3;              // 0..3
    const int m0   = blockIdx.x * G1_MT;

    // W1 -> smem, zero-pad rows 1433..1439 (single barrier in whole kernel)
    {
        const float4* W4  = (const float4*)W1;
        float4*       ws4 = (float4*)ws;
        const int nW = K_IN * C1 / 4;
        const int nP = WS_FLOATS / 4;
        for (int i = tid; i < nP; i += G1_BLOCK) {
            float4 v = make_float4(0.f, 0.f, 0.f, 0.f);
            if (i < nW) v = W4[i];
            ws4[i] = v;
        }
    }

    // per-lane global source offsets for the 24 copies (rows rowb+4j)
    unsigned offu[24];
#pragma unroll
    for (int j = 0; j < 24; j++) {
        int grow = m0 + RPW * w + rowb + 4 * j;
        if (grow > N_NODES - 1) grow = N_NODES - 1;      // clamp; masked at store
        offu[j] = (unsigned)grow * K_IN + kk;
    }
    float* wxs = xs + w * (STAGES * STG_F);
    const unsigned wxs_u32 = (unsigned)__cvta_generic_to_shared(wxs);
    const unsigned dstc = wxs_u32 + (unsigned)(kk * RPW + rowb) * 4u;

    unsigned long long acc2[3][8];
#pragma unroll
    for (int r = 0; r < 3; r++)
#pragma unroll
        for (int c = 0; c < 8; c++) acc2[r][c] = 0ull;

    __syncthreads();   // ws visible; warps decouple from here on

    // prologue: issue tiles 0..2 (all k valid: t < 179)
#pragma unroll
    for (int t = 0; t < 3; t++) {
        unsigned d0 = dstc + (unsigned)(t * STG_F) * 4u;
        const float* src = x + 8 * t;
#pragma unroll
        for (int j = 0; j < 24; j++)
            cp_async4(d0 + 16u * (unsigned)(j ^ kk), src + offu[j]);
        cp_commit();
    }

    for (int t = 0; t < G1_NT; t++) {
        cp_wait2();            // own group for tile t done
        __syncwarp();          // make lane-mates' staging writes visible

        // issue tile t+3 into stage (t+3)&3 (its previous tile t-1 is fully
        // consumed: every lane passed iteration t-1's compute before this
        // iteration's syncwarp)
        if (t + 3 < G1_NT) {
            int tn = t + 3;
            unsigned d0 = dstc + (unsigned)((tn & 3) * STG_F) * 4u;
            const float* src = x + 8 * tn;
            bool kv = (8 * tn + kk) < K_IN;   // false only for tn=179, kk>0
            if (kv) {
#pragma unroll
                for (int j = 0; j < 24; j++)
                    cp_async4(d0 + 16u * (unsigned)(j ^ kk), src + offu[j]);
            }
        }
        cp_commit();

        const float* xb = wxs + (t & 3) * STG_F;
#pragma unroll
        for (int k = 0; k < 8; k++) {
            const ulonglong2* wrow = (const ulonglong2*)(ws + (t * 8 + k) * C1);
            ulonglong2 wa = wrow[0], wb = wrow[1], wc = wrow[2], wd = wrow[3];
            const int lx = (lane ^ (4 * k)) + k * RPW;
#pragma unroll
            for (int r = 0; r < 3; r++) {
                float xv = xb[lx + 32 * r];
                unsigned long long xv2;
                asm("mov.b64 %0, {%1, %1};" : "=l"(xv2) : "f"(xv));
                ffma2(acc2[r][0], xv2, wa.x);
                ffma2(acc2[r][1], xv2, wa.y);
                ffma2(acc2[r][2], xv2, wb.x);
                ffma2(acc2[r][3], xv2, wb.y);
                ffma2(acc2[r][4], xv2, wc.x);
                ffma2(acc2[r][5], xv2, wc.y);
                ffma2(acc2[r][6], xv2, wd.x);
                ffma2(acc2[r][7], xv2, wd.y);
            }
        }
    }

    // store h1 (rows lane+32r of this warp's 96-row block)
#pragma unroll
    for (int r = 0; r < 3; r++) {
        int m = m0 + RPW * w + lane + 32 * r;
        if (m < N_NODES) {
            float4* o = (float4*)(g_h1 + (size_t)m * 16);
#pragma unroll
            for (int p = 0; p < 4; p++) {
                float2 f0, f1;
                asm("mov.b64 {%0, %1}, %2;" : "=f"(f0.x), "=f"(f0.y) : "l"(acc2[r][2 * p]));
                asm("mov.b64 {%0, %1}, %2;" : "=f"(f1.x), "=f"(f1.y) : "l"(acc2[r][2 * p + 1]));
                o[p] = make_float4(f0.x, f0.y, f1.x, f1.y);
            }
        }
    }
}

// -------- aggregation 1 + bias + relu + GEMM2 fused: ONE WARP PER NODE -------
__global__ void __launch_bounds__(256)
k_agg1(const float* __restrict__ b1, const float* __restrict__ W2) {
    __shared__ float w2s[16 * 7];
    if (threadIdx.x < 16 * 7) w2s[threadIdx.x] = W2[threadIdx.x];
    __syncthreads();

    int g = (blockIdx.x * blockDim.x + threadIdx.x) >> 5;
    if (g >= N_NODES) return;
    int lane = threadIdx.x & 31;
    int e = lane >> 2, q = lane & 3;

    int s = g_off[g];
    int deg = g_off[g + 1] - s;
    const int* cols = g_ecol + s;

    float4 acc = make_float4(0.f, 0.f, 0.f, 0.f);
    for (int i = e; i < deg; i += 8) {
        int c = __ldg(cols + i);
        float dw = g_dinv[c];
        float4 hv = *(const float4*)(g_h1 + (size_t)c * 16 + q * 4);
        acc.x += hv.x * dw; acc.y += hv.y * dw;
        acc.z += hv.z * dw; acc.w += hv.w * dw;
    }

#pragma unroll
    for (int o = 16; o >= 4; o >>= 1) {
        acc.x += __shfl_xor_sync(0xffffffffu, acc.x, o);
        acc.y += __shfl_xor_sync(0xffffffffu, acc.y, o);
        acc.z += __shfl_xor_sync(0xffffffffu, acc.z, o);
        acc.w += __shfl_xor_sync(0xffffffffu, acc.w, o);
    }

    float di = g_dinv[g];
    float4 self = *(const float4*)(g_h1 + (size_t)g * 16 + q * 4);
    float4 bb   = ((const float4*)b1)[q];
    float v0 = fmaxf(bb.x + di * (acc.x + di * self.x), 0.f);
    float v1 = fmaxf(bb.y + di * (acc.y + di * self.y), 0.f);
    float v2 = fmaxf(bb.z + di * (acc.z + di * self.z), 0.f);
    float v3 = fmaxf(bb.w + di * (acc.w + di * self.w), 0.f);

    float h2a[7];
    const float* w2r = w2s + (4 * q) * 7;
#pragma unroll
    for (int c2 = 0; c2 < 7; c2++)
        h2a[c2] = v0 * w2r[c2] + v1 * w2r[7 + c2] + v2 * w2r[14 + c2] + v3 * w2r[21 + c2];
#pragma unroll
    for (int o = 1; o <= 2; o <<= 1)
#pragma unroll
        for (int c2 = 0; c2 < 7; c2++)
            h2a[c2] += __shfl_xor_sync(0xffffffffu, h2a[c2], o);

    if (lane == 0) {
        float4* o4 = (float4*)(g_h2 + (size_t)g * 8);
        o4[0] = make_float4(h2a[0], h2a[1], h2a[2], h2a[3]);
        o4[1] = make_float4(h2a[4], h2a[5], h2a[6], 0.f);
    }
}

// -------- aggregation 2 + bias + log_softmax: ONE WARP PER NODE --------------
__global__ void __launch_bounds__(256)
k_agg2(const float* __restrict__ b2, float* __restrict__ out) {
    int g = (blockIdx.x * blockDim.x + threadIdx.x) >> 5;
    if (g >= N_NODES) return;
    int lane = threadIdx.x & 31;
    int e = lane >> 2, q = lane & 3;

    int s = g_off[g];
    int deg = g_off[g + 1] - s;
    const int* cols = g_ecol + s;

    float a0 = 0.f, a1 = 0.f;
    for (int i = e; i < deg; i += 8) {
        int c = __ldg(cols + i);
        float dw = g_dinv[c];
        float2 hv = *(const float2*)(g_h2 + (size_t)c * 8 + q * 2);
        a0 += hv.x * dw;
        a1 += hv.y * dw;
    }
#pragma unroll
    for (int o = 16; o >= 4; o >>= 1) {
        a0 += __shfl_xor_sync(0xffffffffu, a0, o);
        a1 += __shfl_xor_sync(0xffffffffu, a1, o);
    }

    float di = g_dinv[g];
    float dd = di * di;
    float2 self = *(const float2*)(g_h2 + (size_t)g * 8 + q * 2);
    float bb0 = b2[2 * q];
    float bb1 = (q < 3) ? b2[2 * q + 1] : 0.f;
    a0 = bb0 + di * a0 + dd * self.x;
    a1 = bb1 + di * a1 + dd * self.y;

    float m = (q == 3) ? a0 : fmaxf(a0, a1);
    m = fmaxf(m, __shfl_xor_sync(0xffffffffu, m, 1, 4));
    m = fmaxf(m, __shfl_xor_sync(0xffffffffu, m, 2, 4));
    float e0 = expf(a0 - m);
    float e1 = (q == 3) ? 0.f : expf(a1 - m);
    float ss = e0 + e1;
    ss += __shfl_xor_sync(0xffffffffu, ss, 1, 4);
    ss += __shfl_xor_sync(0xffffffffu, ss, 2, 4);
    float ls = m + logf(ss);

    if (e == 0) {
        out[(size_t)g * 7 + 2 * q] = a0 - ls;
        if (q < 3) out[(size_t)g * 7 + 2 * q + 1] = a1 - ls;
    }
}

// ---------------- launch ------------------------------------------------------
static cudaStream_t s_csr = 0;
static cudaEvent_t  ev_fork = 0, ev_join = 0;

extern "C" void kernel_launch(void* const* d_in, const int* in_sizes, int n_in,
                              void* d_out, int out_size) {
    const float* x   = (const float*)d_in[0];
    const int*   row = (const int*)  d_in[1];
    const int*   col = (const int*)  d_in[2];
    const float* W1  = (const float*)d_in[3];
    const float* b1  = (const float*)d_in[4];
    const float* W2  = (const float*)d_in[5];
    const float* b2  = (const float*)d_in[6];
    float* out = (float*)d_out;

    if (!s_csr) {
        cudaStreamCreateWithFlags(&s_csr, cudaStreamNonBlocking);
        cudaEventCreateWithFlags(&ev_fork, cudaEventDisableTiming);
        cudaEventCreateWithFlags(&ev_join, cudaEventDisableTiming);
        cudaFuncSetAttribute(k_gemm1, cudaFuncAttributeMaxDynamicSharedMemorySize,
                             G1_SMEM_BYTES);
    }

    // fork: CSR chain onto side stream (overlaps with GEMM1)
    cudaEventRecord(ev_fork, 0);
    cudaStreamWaitEvent(s_csr, ev_fork, 0);

    k_zero_cnt<<<(N_NODES / 4 + 255) / 256, 256, 0, s_csr>>>();
    k_count   <<<(N_EDGES / 8 + 255) / 256, 256, 0, s_csr>>>(row);
    k_scan    <<<1, 1024, 0, s_csr>>>();

    // main stream: GEMM1 (4th submission -> profiled slot)
    k_gemm1<<<G1_GRID, G1_BLOCK, G1_SMEM_BYTES>>>(x, W1);

    k_place<<<(N_EDGES / 8 + 255) / 256, 256, 0, s_csr>>>(row, col);

    // join: aggregation needs both CSR and h1
    cudaEventRecord(ev_join, s_csr);
    cudaStreamWaitEvent(0, ev_join, 0);

    k_agg1<<<(N_NODES * 32 + 255) / 256, 256>>>(b1, W2);
    k_agg2<<<(N_NODES * 32 + 255) / 256, 256>>>(b2, out);
}